// round 4
// baseline (speedup 1.0000x reference)
#include <cuda_runtime.h>

#define B_WIN 2048
#define NTOK  98
#define NHEAD 4
#define HD    32
#define C3    384
#define DIMM  128
#define NWIN  64
#define NN    (NTOK * NTOK)   // 9604
#define RPB_ROWS 507
#define ATS   104             // At row stride in floats (float4-aligned, even)

typedef unsigned long long ull;

__device__ __forceinline__ ull pk2(float lo, float hi) {
    ull r; asm("mov.b64 %0, {%1,%2};" : "=l"(r) : "f"(lo), "f"(hi)); return r;
}
__device__ __forceinline__ float2 upk2(ull v) {
    float2 f; asm("mov.b64 {%0,%1}, %2;" : "=f"(f.x), "=f"(f.y) : "l"(v)); return f;
}
__device__ __forceinline__ void fma2(ull& d, ull a, ull b) {
    asm("fma.rn.f32x2 %0, %1, %2, %0;" : "+l"(d) : "l"(a), "l"(b));
}
__device__ __forceinline__ ull add2(ull a, ull b) {
    ull r; asm("add.rn.f32x2 %0, %1, %2;" : "=l"(r) : "l"(a), "l"(b)); return r;
}

// Scratch (device globals: allocation-free rule)
__device__ float g_bm[(size_t)NWIN * NHEAD * NN];     // bias + mask, 9.8 MB
__device__ float g_tmp[(size_t)B_WIN * NTOK * DIMM];  // attention output, 103 MB

// ---------------------------------------------------------------------------
// Kernel A: g_bm[w][h][q*98+k] = rpb_table[rpi[q,k]][h] + mask[w][q][k]
// rpi is int32 on the wire.
// ---------------------------------------------------------------------------
__global__ void bm_kernel(const int* __restrict__ rpi,
                          const float* __restrict__ table,
                          const float* __restrict__ mask) {
    int i = blockIdx.x * blockDim.x + threadIdx.x;
    if (i >= NWIN * NN) return;
    int w = i / NN;
    int e = i - w * NN;
    int r = rpi[e];
    r = (r < 0) ? 0 : (r >= RPB_ROWS ? RPB_ROWS - 1 : r);
    float mk = mask[(size_t)w * NN + e];
#pragma unroll
    for (int h = 0; h < NHEAD; h++) {
        g_bm[((size_t)w * NHEAD + h) * NN + e] = table[r * NHEAD + h] + mk;
    }
}

// ---------------------------------------------------------------------------
// Kernel B: attention per (window b, head h). 256 threads. FFMA2 (f32x2).
// smem (floats): At[98][104] | Qd[100][32] ull (dup pairs) | Ktf[32][130] | Vs2[49][32] ull
// ---------------------------------------------------------------------------
__global__ __launch_bounds__(256) void attn_kernel(const float* __restrict__ x) {
    extern __shared__ float sm[];
    float* At  = sm;                         // 98*104 = 10192 floats
    ull*   Qd  = (ull*)(sm + 10192);         // [100][32] packed (q,q)  (6400 floats)
    float* Ktf = sm + 16592;                 // [32][130] k-major        (4160 floats)
    ull*   Ktu = (ull*)Ktf;                  // row stride 65 ull
    ull*   Vs2 = (ull*)(sm + 20752);         // [49][32] packed (v_{2k},v_{2k+1}) (3136 floats)
    ull*   Atu = (ull*)At;                   // row stride 52 ull

    const int h = blockIdx.x;
    const int b = blockIdx.y;
    const int tid  = threadIdx.x;
    const int lane = tid & 31;
    const int wid  = tid >> 5;

    const float scale = 0.17677669529663687f;  // 1/sqrt(32)
    const float* xb = x + (size_t)b * NTOK * C3;

    // ---- load Q (scaled, duplicated), K (k-major), V (k-paired) ----
    for (int i = tid; i < NTOK * HD; i += 256) {
        int q = i >> 5, d = i & 31;          // d == lane
        const float* p = xb + q * C3 + h * HD + d;
        float qv = p[0] * scale;
        Qd[q * 32 + d] = pk2(qv, qv);
        Ktf[d * 130 + q] = p[DIMM];
        ((float*)Vs2)[((q >> 1) * 32 + d) * 2 + (q & 1)] = p[2 * DIMM];
    }
    // zero pads: Q rows 98,99 ; Kt cols 98..129
    if (tid < 64) Qd[(98 + (tid >> 5)) * 32 + (tid & 31)] = 0ull;
    for (int i = tid; i < 32 * 32; i += 256) {
        int d = i >> 5, kk = 98 + (i & 31);
        Ktf[d * 130 + kk] = 0.0f;
    }
    __syncthreads();

    // ---- QK^T + bias+mask -> At (packed pairs along k) ----
    const size_t bmbase = ((size_t)(b & (NWIN - 1)) * NHEAD + h) * NN;
    for (int qg = wid; qg < 25; qg += 8) {
        int q0 = qg * 4;
        ull acc[4][2];
#pragma unroll
        for (int j = 0; j < 4; j++) { acc[j][0] = 0ull; acc[j][1] = 0ull; }

#pragma unroll 4
        for (int d = 0; d < HD; d++) {
            ull kv0 = Ktu[d * 65 + lane];        // k = 2*lane, 2*lane+1
            ull kv1 = Ktu[d * 65 + 32 + lane];   // k = 64+2*lane, 65+2*lane
#pragma unroll
            for (int j = 0; j < 4; j++) {
                ull qp = Qd[(q0 + j) * 32 + d];
                fma2(acc[j][0], qp, kv0);
                fma2(acc[j][1], qp, kv1);
            }
        }
#pragma unroll
        for (int j = 0; j < 4; j++) {
            int q = q0 + j;
            if (q < NTOK) {
                const ull* bm = (const ull*)(g_bm + bmbase + (size_t)q * NTOK);
                Atu[q * 52 + lane] = add2(acc[j][0], bm[lane]);
                if (lane < 17)   // k = 64+2*lane <= 97
                    Atu[q * 52 + 32 + lane] = add2(acc[j][1], bm[32 + lane]);
            }
        }
    }
    __syncthreads();

    // ---- softmax per row (warp per row) ----
    for (int q = wid; q < NTOK; q += 8) {
        float* row = At + q * ATS;
        float v0 = row[lane];
        float v1 = row[lane + 32];
        float v2 = row[lane + 64];
        float v3 = (lane < 2) ? row[lane + 96] : -3.0e38f;
        float m = fmaxf(fmaxf(v0, v1), fmaxf(v2, v3));
#pragma unroll
        for (int off = 16; off > 0; off >>= 1)
            m = fmaxf(m, __shfl_xor_sync(0xffffffffu, m, off));
        float e0 = __expf(v0 - m);
        float e1 = __expf(v1 - m);
        float e2 = __expf(v2 - m);
        float e3 = (lane < 2) ? __expf(v3 - m) : 0.0f;
        float s = e0 + e1 + e2 + e3;
#pragma unroll
        for (int off = 16; off > 0; off >>= 1)
            s += __shfl_xor_sync(0xffffffffu, s, off);
        float inv = __frcp_rn(s);
        row[lane]      = e0 * inv;
        row[lane + 32] = e1 * inv;
        row[lane + 64] = e2 * inv;
        if (lane < 2) row[lane + 96] = e3 * inv;
    }
    __syncthreads();

    // ---- PV (packed pairs along k): lane owns d = lane ----
    {
        ull acc2[13];
#pragma unroll
        for (int j = 0; j < 13; j++) acc2[j] = 0ull;

        const ulonglong2* At2 = (const ulonglong2*)At;   // row stride 26 (16B units)
        for (int kp2 = 0; kp2 < 24; kp2++) {             // k = 4*kp2 .. 4*kp2+3
            ull vkA = Vs2[(2 * kp2) * 32 + lane];
            ull vkB = Vs2[(2 * kp2 + 1) * 32 + lane];
#pragma unroll
            for (int j = 0; j < 13; j++) {
                int q = wid + 8 * j;
                if (q < NTOK) {
                    ulonglong2 a = At2[q * 26 + kp2];    // broadcast v2.u64
                    fma2(acc2[j], a.x, vkA);
                    fma2(acc2[j], a.y, vkB);
                }
            }
        }
        {   // tail k = 96,97  (pair index 48)
            ull vkT = Vs2[48 * 32 + lane];
#pragma unroll
            for (int j = 0; j < 13; j++) {
                int q = wid + 8 * j;
                if (q < NTOK) fma2(acc2[j], Atu[q * 52 + 48], vkT);
            }
        }
#pragma unroll
        for (int j = 0; j < 13; j++) {
            int q = wid + 8 * j;
            if (q < NTOK) {
                float2 f = upk2(acc2[j]);
                g_tmp[((size_t)b * NTOK + q) * DIMM + h * HD + lane] = f.x + f.y;
            }
        }
    }
}

// ---------------------------------------------------------------------------
// Kernel C: projection  out[r][c] = sum_d g_tmp[r][d] * W[c][d] + b[c]
// FFMA2 packed along d.
// ---------------------------------------------------------------------------
__global__ __launch_bounds__(256) void proj_kernel(const float* __restrict__ pw,
                                                   const float* __restrict__ pb,
                                                   float* __restrict__ out) {
    extern __shared__ float sm[];
    float* Ws = sm;                 // [128][129] : Ws[d*129+c] = W[c][d]
    float* Is = sm + 128 * 129;     // [32][128]

    const int tid = threadIdx.x;
    const size_t row0 = (size_t)blockIdx.x * 32;

    for (int i = tid; i < DIMM * DIMM; i += 256) {
        int c = i >> 7, d = i & 127;
        Ws[d * 129 + c] = pw[i];
    }
    for (int i = tid; i < 32 * DIMM; i += 256)
        Is[i] = g_tmp[row0 * DIMM + i];
    __syncthreads();

    const int c  = tid & 127;
    const int rh = tid >> 7;
    const ulonglong2* Is2 = (const ulonglong2*)Is;   // row stride 32 (16B units)

    ull acc[16];
#pragma unroll
    for (int j = 0; j < 16; j++) acc[j] = 0ull;

    for (int d0 = 0; d0 < DIMM; d0 += 8) {
        ull w0 = pk2(Ws[(d0 + 0) * 129 + c], Ws[(d0 + 1) * 129 + c]);
        ull w1 = pk2(Ws[(d0 + 2) * 129 + c], Ws[(d0 + 3) * 129 + c]);
        ull w2 = pk2(Ws[(d0 + 4) * 129 + c], Ws[(d0 + 5) * 129 + c]);
        ull w3 = pk2(Ws[(d0 + 6) * 129 + c], Ws[(d0 + 7) * 129 + c]);
#pragma unroll
        for (int j = 0; j < 16; j++) {
            int row = rh * 16 + j;
            ulonglong2 pA = Is2[row * 32 + (d0 >> 2)];
            ulonglong2 pB = Is2[row * 32 + (d0 >> 2) + 1];
            fma2(acc[j], pA.x, w0);
            fma2(acc[j], pA.y, w1);
            fma2(acc[j], pB.x, w2);
            fma2(acc[j], pB.y, w3);
        }
    }
    float bias = pb[c];
#pragma unroll
    for (int j = 0; j < 16; j++) {
        float2 f = upk2(acc[j]);
        out[(row0 + rh * 16 + j) * DIMM + c] = f.x + f.y + bias;
    }
}

// ---------------------------------------------------------------------------
extern "C" void kernel_launch(void* const* d_in, const int* in_sizes, int n_in,
                              void* d_out, int out_size) {
    const float* x     = (const float*)d_in[0];
    const int*   rpi   = (const int*)d_in[1];      // int32 on the wire
    const float* mask  = (const float*)d_in[2];
    const float* table = (const float*)d_in[3];
    const float* pw    = (const float*)d_in[4];
    const float* pb    = (const float*)d_in[5];
    float*       out   = (float*)d_out;

    const int smem_attn = 23888 * 4;                 // 95552 B
    const int smem_proj = (128 * 129 + 32 * 128) * 4;  // 82432 B
    cudaFuncSetAttribute(attn_kernel, cudaFuncAttributeMaxDynamicSharedMemorySize, smem_attn);
    cudaFuncSetAttribute(proj_kernel, cudaFuncAttributeMaxDynamicSharedMemorySize, smem_proj);

    bm_kernel<<<(NWIN * NN + 255) / 256, 256>>>(rpi, table, mask);
    attn_kernel<<<dim3(NHEAD, B_WIN), 256, smem_attn>>>(x);
    proj_kernel<<<(B_WIN * NTOK) / 32, 256, smem_proj>>>(pw, pb, out);
}

// round 5
// speedup vs baseline: 4.4523x; 4.4523x over previous
#include <cuda_runtime.h>

#define B_WIN 2048
#define NTOK  98
#define NHEAD 4
#define HD    32
#define C3    384
#define DIMM  128
#define NWIN  64
#define NN    (NTOK * NTOK)   // 9604
#define RPB_ROWS 507

typedef unsigned int uint;

// ---------------- bf16 helpers ----------------
__device__ __forceinline__ uint pkbf(float lo, float hi) {
    uint r; asm("cvt.rn.bf16x2.f32 %0, %1, %2;" : "=r"(r) : "f"(hi), "f"(lo)); return r;
}
__device__ __forceinline__ float blo(uint p) { return __uint_as_float(p << 16); }
__device__ __forceinline__ float bhi(uint p) { return __uint_as_float(p & 0xffff0000u); }

// D += A * B  (m16n8k16, bf16 in, f32 accum)
__device__ __forceinline__ void mma16816(float* d, const uint* a, uint b0, uint b1) {
    asm("mma.sync.aligned.m16n8k16.row.col.f32.bf16.bf16.f32 "
        "{%0,%1,%2,%3}, {%4,%5,%6,%7}, {%8,%9}, {%0,%1,%2,%3};"
        : "+f"(d[0]), "+f"(d[1]), "+f"(d[2]), "+f"(d[3])
        : "r"(a[0]), "r"(a[1]), "r"(a[2]), "r"(a[3]), "r"(b0), "r"(b1));
}

// ---------------- scratch ----------------
__device__ float g_bm[(size_t)NWIN * NHEAD * NN];          // bias + mask (fp32), 9.8 MB
__device__ uint  g_th[(size_t)B_WIN * NTOK * 64];          // attn out hi (bf16x2), 51.4 MB
__device__ uint  g_tl[(size_t)B_WIN * NTOK * 64];          // attn out lo (bf16x2), 51.4 MB

// ---------------------------------------------------------------------------
// Kernel A: g_bm[w][h][q*98+k] = rpb_table[rpi[q,k]][h] + mask[w][q][k]
// ---------------------------------------------------------------------------
__global__ void bm_kernel(const int* __restrict__ rpi,
                          const float* __restrict__ table,
                          const float* __restrict__ mask) {
    int i = blockIdx.x * blockDim.x + threadIdx.x;
    if (i >= NWIN * NN) return;
    int w = i / NN;
    int e = i - w * NN;
    int r = rpi[e];
    r = (r < 0) ? 0 : (r >= RPB_ROWS ? RPB_ROWS - 1 : r);
    float mk = mask[(size_t)w * NN + e];
#pragma unroll
    for (int hh = 0; hh < NHEAD; hh++) {
        g_bm[((size_t)w * NHEAD + hh) * NN + e] = table[r * NHEAD + hh] + mk;
    }
}

// ---------------------------------------------------------------------------
// Kernel B: attention per (window b, head h). 256 threads, 8 warps, m16/warp.
// bf16x3 compensated MMA. smem word offsets:
//  QH 0 [128 rows x 20w]  QL 2560  KH 5120 [112 x 20w]  KL 7360
//  VTH 9600 [32 x 60w]    VTL 11520   total 13440 words (53760 B)
// ---------------------------------------------------------------------------
#define QH  0
#define QL  2560
#define KH  5120
#define KL  7360
#define VTH 9600
#define VTL 11520
#define SMW 13440

__global__ __launch_bounds__(256, 2) void attn_kernel(const float* __restrict__ x) {
    extern __shared__ uint smw[];

    const int h   = blockIdx.x;
    const int b   = blockIdx.y;
    const int tid = threadIdx.x;
    const int lane = tid & 31;
    const int wid  = tid >> 5;
    const int g = lane >> 2;     // group (row within tile)
    const int t = lane & 3;      // thread in group

    const float scale = 0.17677669529663687f;  // 1/sqrt(32)
    const float* xb = x + (size_t)b * NTOK * C3;

    // ---- zero smem (covers all pads) ----
    for (int i = tid; i < SMW; i += 256) smw[i] = 0u;
    __syncthreads();

    // ---- load + split Q(scaled), K, V(transposed) to bf16 hi/lo ----
    for (int i = tid; i < NTOK * 16; i += 256) {       // 1568 float2-pairs
        int q = i >> 4, dp = i & 15;
        const float* base = xb + q * C3 + h * HD + 2 * dp;
        float2 qv = *(const float2*)base;
        qv.x *= scale; qv.y *= scale;
        uint hq = pkbf(qv.x, qv.y);
        smw[QH + q * 20 + dp] = hq;
        smw[QL + q * 20 + dp] = pkbf(qv.x - blo(hq), qv.y - bhi(hq));
        float2 kv = *(const float2*)(base + DIMM);
        uint hk = pkbf(kv.x, kv.y);
        smw[KH + q * 20 + dp] = hk;
        smw[KL + q * 20 + dp] = pkbf(kv.x - blo(hk), kv.y - bhi(hk));
        float2 vv = *(const float2*)(base + 2 * DIMM);
        uint hv = pkbf(vv.x, vv.y);
        uint lv = pkbf(vv.x - blo(hv), vv.y - bhi(hv));
        // transposed scatter: Vt[d][token], halfword stores
        unsigned short* vth = (unsigned short*)(smw + VTH);
        unsigned short* vtl = (unsigned short*)(smw + VTL);
        int d0 = 2 * dp;
        vth[d0 * 120 + q]       = (unsigned short)(hv & 0xffffu);
        vth[(d0 + 1) * 120 + q] = (unsigned short)(hv >> 16);
        vtl[d0 * 120 + q]       = (unsigned short)(lv & 0xffffu);
        vtl[(d0 + 1) * 120 + q] = (unsigned short)(lv >> 16);
    }
    __syncthreads();

    if (wid == 7) return;   // rows 112-127: all padding, no barriers remain

    const int r0 = wid * 16 + g;   // this thread's rows: r0 and r0+8
    const int q1 = r0 + 8;

    // ---- S = Q K^T  (14 n8-tiles, K-dim 32 = 2 k16 steps, 3-MMA comp) ----
    float S[14][4];
#pragma unroll
    for (int nt = 0; nt < 14; nt++)
#pragma unroll
        for (int j = 0; j < 4; j++) S[nt][j] = 0.0f;

#pragma unroll
    for (int s = 0; s < 2; s++) {
        int ab = r0 * 20 + 8 * s + t;
        uint ah[4] = { smw[QH + ab], smw[QH + ab + 160], smw[QH + ab + 4], smw[QH + ab + 164] };
        uint al[4] = { smw[QL + ab], smw[QL + ab + 160], smw[QL + ab + 4], smw[QL + ab + 164] };
#pragma unroll
        for (int nt = 0; nt < 14; nt++) {
            int kb = (8 * nt + g) * 20 + 8 * s + t;
            uint bh0 = smw[KH + kb], bh1 = smw[KH + kb + 4];
            uint bl0 = smw[KL + kb], bl1 = smw[KL + kb + 4];
            mma16816(S[nt], ah, bh0, bh1);
            mma16816(S[nt], ah, bl0, bl1);
            mma16816(S[nt], al, bh0, bh1);
        }
    }

    // ---- bias + mask + column masking ----
    const float* bmp = g_bm + ((size_t)(b & (NWIN - 1)) * NHEAD + h) * NN;
#pragma unroll
    for (int nt = 0; nt < 14; nt++) {
        int c0 = nt * 8 + 2 * t;
        bool cok = (c0 < NTOK);   // pair fully valid iff c0<98 (c0 even)
        if (r0 < NTOK && cok) {
            float2 bb = __ldg((const float2*)(bmp + r0 * NTOK + c0));
            S[nt][0] += bb.x; S[nt][1] += bb.y;
        } else { S[nt][0] = -1e30f; S[nt][1] = -1e30f; }
        if (q1 < NTOK && cok) {
            float2 bb = __ldg((const float2*)(bmp + q1 * NTOK + c0));
            S[nt][2] += bb.x; S[nt][3] += bb.y;
        } else { S[nt][2] = -1e30f; S[nt][3] = -1e30f; }
    }

    // ---- softmax (rows r0 and q1, each spread over a lane-quad) ----
    float m0 = -1e30f, m1 = -1e30f;
#pragma unroll
    for (int nt = 0; nt < 14; nt++) {
        m0 = fmaxf(m0, fmaxf(S[nt][0], S[nt][1]));
        m1 = fmaxf(m1, fmaxf(S[nt][2], S[nt][3]));
    }
    m0 = fmaxf(m0, __shfl_xor_sync(0xffffffffu, m0, 1));
    m0 = fmaxf(m0, __shfl_xor_sync(0xffffffffu, m0, 2));
    m1 = fmaxf(m1, __shfl_xor_sync(0xffffffffu, m1, 1));
    m1 = fmaxf(m1, __shfl_xor_sync(0xffffffffu, m1, 2));
    float s0 = 0.0f, s1 = 0.0f;
#pragma unroll
    for (int nt = 0; nt < 14; nt++) {
        S[nt][0] = __expf(S[nt][0] - m0); s0 += S[nt][0];
        S[nt][1] = __expf(S[nt][1] - m0); s0 += S[nt][1];
        S[nt][2] = __expf(S[nt][2] - m1); s1 += S[nt][2];
        S[nt][3] = __expf(S[nt][3] - m1); s1 += S[nt][3];
    }
    s0 += __shfl_xor_sync(0xffffffffu, s0, 1);
    s0 += __shfl_xor_sync(0xffffffffu, s0, 2);
    s1 += __shfl_xor_sync(0xffffffffu, s1, 1);
    s1 += __shfl_xor_sync(0xffffffffu, s1, 2);
    float inv0 = __frcp_rn(s0), inv1 = __frcp_rn(s1);

    // ---- pack P to bf16 hi/lo fragments (accum layout == A layout) ----
    uint ph[14][2], pl[14][2];
#pragma unroll
    for (int nt = 0; nt < 14; nt++) {
        float f0 = S[nt][0] * inv0, f1 = S[nt][1] * inv0;
        uint hp = pkbf(f0, f1);
        ph[nt][0] = hp;
        pl[nt][0] = pkbf(f0 - blo(hp), f1 - bhi(hp));
        float f2 = S[nt][2] * inv1, f3 = S[nt][3] * inv1;
        uint hq = pkbf(f2, f3);
        ph[nt][1] = hq;
        pl[nt][1] = pkbf(f2 - blo(hq), f3 - bhi(hq));
    }

    // ---- O = P V  (K-dim 112 = 7 k16 steps, 4 n8-tiles of d) ----
    float O[4][4];
#pragma unroll
    for (int nt = 0; nt < 4; nt++)
#pragma unroll
        for (int j = 0; j < 4; j++) O[nt][j] = 0.0f;

#pragma unroll
    for (int s = 0; s < 7; s++) {
        uint pah[4] = { ph[2 * s][0], ph[2 * s][1], ph[2 * s + 1][0], ph[2 * s + 1][1] };
        uint pal[4] = { pl[2 * s][0], pl[2 * s][1], pl[2 * s + 1][0], pl[2 * s + 1][1] };
#pragma unroll
        for (int nt = 0; nt < 4; nt++) {
            int vb = (8 * nt + g) * 60 + 8 * s + t;
            uint bh0 = smw[VTH + vb], bh1 = smw[VTH + vb + 4];
            uint bl0 = smw[VTL + vb], bl1 = smw[VTL + vb + 4];
            mma16816(O[nt], pah, bh0, bh1);
            mma16816(O[nt], pah, bl0, bl1);
            mma16816(O[nt], pal, bh0, bh1);
        }
    }

    // ---- store O as bf16 hi/lo pairs to g_th/g_tl ----
    const size_t obase = (size_t)b * NTOK * 64 + h * 16;
#pragma unroll
    for (int nt = 0; nt < 4; nt++) {
        int dw = nt * 4 + t;   // word offset within the 16-word head slot
        if (r0 < NTOK) {
            uint hw_ = pkbf(O[nt][0], O[nt][1]);
            g_th[obase + (size_t)r0 * 64 + dw] = hw_;
            g_tl[obase + (size_t)r0 * 64 + dw] = pkbf(O[nt][0] - blo(hw_), O[nt][1] - bhi(hw_));
        }
        if (q1 < NTOK) {
            uint hw_ = pkbf(O[nt][2], O[nt][3]);
            g_th[obase + (size_t)q1 * 64 + dw] = hw_;
            g_tl[obase + (size_t)q1 * 64 + dw] = pkbf(O[nt][2] - blo(hw_), O[nt][3] - bhi(hw_));
        }
    }
}

// ---------------------------------------------------------------------------
// Kernel C: projection  out[r][c] = sum_d A[r][d] * W[c][d] + pb[c]
// A = g_th/g_tl (bf16 hi/lo), W split in smem. 128 rows x 128 cols per block.
// smem: Wh [128 x 68w] at 0, Wl at 8704; total 17408 words (69632 B)
// ---------------------------------------------------------------------------
__global__ __launch_bounds__(256, 2) void proj_kernel(const float* __restrict__ pw,
                                                      const float* __restrict__ pb,
                                                      float* __restrict__ out) {
    extern __shared__ uint ws[];
    const int tid = threadIdx.x;
    const int lane = tid & 31;
    const int wid  = tid >> 5;
    const int g = lane >> 2, t = lane & 3;

    for (int i = tid; i < 8192; i += 256) {   // 128 x 64 float2-pairs
        int c = i >> 6, dp = i & 63;
        float2 w = *(const float2*)(pw + c * DIMM + 2 * dp);
        uint hw_ = pkbf(w.x, w.y);
        ws[c * 68 + dp]        = hw_;
        ws[8704 + c * 68 + dp] = pkbf(w.x - blo(hw_), w.y - bhi(hw_));
    }
    __syncthreads();

    const size_t r0 = (size_t)blockIdx.x * 128 + wid * 16 + g;
    const size_t r1 = r0 + 8;

    float O[16][4];
#pragma unroll
    for (int nt = 0; nt < 16; nt++)
#pragma unroll
        for (int j = 0; j < 4; j++) O[nt][j] = 0.0f;

#pragma unroll
    for (int s = 0; s < 8; s++) {
        uint ah[4] = { g_th[r0 * 64 + 8 * s + t], g_th[r1 * 64 + 8 * s + t],
                       g_th[r0 * 64 + 8 * s + t + 4], g_th[r1 * 64 + 8 * s + t + 4] };
        uint al[4] = { g_tl[r0 * 64 + 8 * s + t], g_tl[r1 * 64 + 8 * s + t],
                       g_tl[r0 * 64 + 8 * s + t + 4], g_tl[r1 * 64 + 8 * s + t + 4] };
#pragma unroll
        for (int nt = 0; nt < 16; nt++) {
            int wb = (8 * nt + g) * 68 + 8 * s + t;
            uint bh0 = ws[wb], bh1 = ws[wb + 4];
            uint bl0 = ws[8704 + wb], bl1 = ws[8704 + wb + 4];
            mma16816(O[nt], ah, bh0, bh1);
            mma16816(O[nt], ah, bl0, bl1);
            mma16816(O[nt], al, bh0, bh1);
        }
    }

#pragma unroll
    for (int nt = 0; nt < 16; nt++) {
        int c0 = nt * 8 + 2 * t;
        float2 bb = __ldg((const float2*)(pb + c0));
        float2 o0 = { O[nt][0] + bb.x, O[nt][1] + bb.y };
        float2 o1 = { O[nt][2] + bb.x, O[nt][3] + bb.y };
        *(float2*)(out + r0 * DIMM + c0) = o0;
        *(float2*)(out + r1 * DIMM + c0) = o1;
    }
}

// ---------------------------------------------------------------------------
extern "C" void kernel_launch(void* const* d_in, const int* in_sizes, int n_in,
                              void* d_out, int out_size) {
    const float* x     = (const float*)d_in[0];
    const int*   rpi   = (const int*)d_in[1];      // int32 on the wire
    const float* mask  = (const float*)d_in[2];
    const float* table = (const float*)d_in[3];
    const float* pw    = (const float*)d_in[4];
    const float* pb    = (const float*)d_in[5];
    float*       out   = (float*)d_out;

    const int smem_attn = SMW * 4;       // 53760 B
    const int smem_proj = 17408 * 4;     // 69632 B
    cudaFuncSetAttribute(attn_kernel, cudaFuncAttributeMaxDynamicSharedMemorySize, smem_attn);
    cudaFuncSetAttribute(proj_kernel, cudaFuncAttributeMaxDynamicSharedMemorySize, smem_proj);

    bm_kernel<<<(NWIN * NN + 255) / 256, 256>>>(rpi, table, mask);
    attn_kernel<<<dim3(NHEAD, B_WIN), 256, smem_attn>>>(x);
    proj_kernel<<<(B_WIN * NTOK) / DIMM, 256, smem_proj>>>(pw, pb, out);
}

// round 6
// speedup vs baseline: 4.6983x; 1.0553x over previous
#include <cuda_runtime.h>

#define B_WIN 2048
#define NTOK  98
#define NHEAD 4
#define HD    32
#define C3    384
#define DIMM  128
#define NWIN  64
#define NN    (NTOK * NTOK)   // 9604
#define RPB_ROWS 507

typedef unsigned int uint;

// ---------------- bf16 helpers ----------------
__device__ __forceinline__ uint pkbf(float lo, float hi) {
    uint r; asm("cvt.rn.bf16x2.f32 %0, %1, %2;" : "=r"(r) : "f"(hi), "f"(lo)); return r;
}
__device__ __forceinline__ float blo(uint p) { return __uint_as_float(p << 16); }
__device__ __forceinline__ float bhi(uint p) { return __uint_as_float(p & 0xffff0000u); }

// D += A * B  (m16n8k16, bf16 in, f32 accum)
__device__ __forceinline__ void mma16816(float* d, const uint* a, uint b0, uint b1) {
    asm("mma.sync.aligned.m16n8k16.row.col.f32.bf16.bf16.f32 "
        "{%0,%1,%2,%3}, {%4,%5,%6,%7}, {%8,%9}, {%0,%1,%2,%3};"
        : "+f"(d[0]), "+f"(d[1]), "+f"(d[2]), "+f"(d[3])
        : "r"(a[0]), "r"(a[1]), "r"(a[2]), "r"(a[3]), "r"(b0), "r"(b1));
}

// ---------------- scratch ----------------
__device__ float g_bm[(size_t)NWIN * NHEAD * NN];   // bias + mask (fp32), 9.8 MB

// smem word offsets (attention phase)
#define QH  0
#define QL  2240
#define KH  4480
#define KL  6720
#define VTH 8960
#define VTL 10880
#define QKVW 12800
// smem word offsets (projection phase, overlays QKV)
#define WH  0
#define WL  8704
#define SMW_TOT 17408   // 69632 B

// ---------------------------------------------------------------------------
// Kernel A: g_bm[w][h][q*98+k] = rpb_table[rpi[q,k]][h] + mask[w][q][k]
// ---------------------------------------------------------------------------
__global__ void bm_kernel(const int* __restrict__ rpi,
                          const float* __restrict__ table,
                          const float* __restrict__ mask) {
    int i = blockIdx.x * blockDim.x + threadIdx.x;
    if (i >= NWIN * NN) return;
    int w = i / NN;
    int e = i - w * NN;
    int r = rpi[e];
    r = (r < 0) ? 0 : (r >= RPB_ROWS ? RPB_ROWS - 1 : r);
    float mk = mask[(size_t)w * NN + e];
#pragma unroll
    for (int hh = 0; hh < NHEAD; hh++) {
        g_bm[((size_t)w * NHEAD + hh) * NN + e] = table[r * NHEAD + hh] + mk;
    }
}

// ---------------------------------------------------------------------------
// Fused kernel: per window b — 4 heads of attention (O accumulated in regs,
// full 128-d), then projection from registers with W split in smem.
// 256 threads, 8 warps (7 compute warps x m16 rows, warp 7 loads/barriers only).
// ---------------------------------------------------------------------------
__global__ __launch_bounds__(256, 2) void fused_kernel(const float* __restrict__ x,
                                                       const float* __restrict__ pw,
                                                       const float* __restrict__ pb,
                                                       float* __restrict__ out) {
    extern __shared__ uint smw[];

    const int b   = blockIdx.x;
    const int tid = threadIdx.x;
    const int lane = tid & 31;
    const int wid  = tid >> 5;
    const int g = lane >> 2;     // row-in-tile group
    const int t = lane & 3;      // thread in group

    const float scale = 0.17677669529663687f;  // 1/sqrt(32)
    const float* xb = x + (size_t)b * NTOK * C3;
    const int r0 = wid * 16 + g;
    const int q1 = r0 + 8;

    // ---- zero QKV region once (covers all row/col pads) ----
    for (int i = tid; i < QKVW; i += 256) smw[i] = 0u;

    // ---- O accumulators: full 128-d for rows r0, q1 ----
    float O[16][4];
#pragma unroll
    for (int nt = 0; nt < 16; nt++)
#pragma unroll
        for (int j = 0; j < 4; j++) O[nt][j] = 0.0f;

#pragma unroll
    for (int h = 0; h < NHEAD; h++) {
        __syncthreads();   // previous head's consumers done (and initial zero visible)

        // ---- load + split Q(scaled), K, V(transposed) to bf16 hi/lo ----
        for (int i = tid; i < NTOK * 16; i += 256) {
            int q = i >> 4, dp = i & 15;
            const float* base = xb + q * C3 + h * HD + 2 * dp;
            float2 qv = *(const float2*)base;
            qv.x *= scale; qv.y *= scale;
            uint hq = pkbf(qv.x, qv.y);
            smw[QH + q * 20 + dp] = hq;
            smw[QL + q * 20 + dp] = pkbf(qv.x - blo(hq), qv.y - bhi(hq));
            float2 kv = *(const float2*)(base + DIMM);
            uint hk = pkbf(kv.x, kv.y);
            smw[KH + q * 20 + dp] = hk;
            smw[KL + q * 20 + dp] = pkbf(kv.x - blo(hk), kv.y - bhi(hk));
            float2 vv = *(const float2*)(base + 2 * DIMM);
            uint hv = pkbf(vv.x, vv.y);
            uint lv = pkbf(vv.x - blo(hv), vv.y - bhi(hv));
            unsigned short* vth = (unsigned short*)(smw + VTH);
            unsigned short* vtl = (unsigned short*)(smw + VTL);
            int d0 = 2 * dp;
            vth[d0 * 120 + q]       = (unsigned short)(hv & 0xffffu);
            vth[(d0 + 1) * 120 + q] = (unsigned short)(hv >> 16);
            vtl[d0 * 120 + q]       = (unsigned short)(lv & 0xffffu);
            vtl[(d0 + 1) * 120 + q] = (unsigned short)(lv >> 16);
        }
        __syncthreads();

        if (wid < 7) {
            // ---- S = Q K^T (14 n8-tiles, 2 k16 steps, 3-MMA compensated) ----
            float S[14][4];
#pragma unroll
            for (int nt = 0; nt < 14; nt++)
#pragma unroll
                for (int j = 0; j < 4; j++) S[nt][j] = 0.0f;

#pragma unroll
            for (int s = 0; s < 2; s++) {
                int ab = r0 * 20 + 8 * s + t;
                uint ah[4] = { smw[QH + ab], smw[QH + ab + 160],
                               smw[QH + ab + 4], smw[QH + ab + 164] };
                uint al[4] = { smw[QL + ab], smw[QL + ab + 160],
                               smw[QL + ab + 4], smw[QL + ab + 164] };
#pragma unroll
                for (int nt = 0; nt < 14; nt++) {
                    int kb = (8 * nt + g) * 20 + 8 * s + t;
                    uint bh0 = smw[KH + kb], bh1 = smw[KH + kb + 4];
                    uint bl0 = smw[KL + kb], bl1 = smw[KL + kb + 4];
                    mma16816(S[nt], ah, bh0, bh1);
                    mma16816(S[nt], ah, bl0, bl1);
                    mma16816(S[nt], al, bh0, bh1);
                }
            }

            // ---- bias + mask + column masking ----
            const float* bmp = g_bm + ((size_t)(b & (NWIN - 1)) * NHEAD + h) * NN;
#pragma unroll
            for (int nt = 0; nt < 14; nt++) {
                int c0 = nt * 8 + 2 * t;
                bool cok = (c0 < NTOK);
                if (r0 < NTOK && cok) {
                    float2 bb = __ldg((const float2*)(bmp + r0 * NTOK + c0));
                    S[nt][0] += bb.x; S[nt][1] += bb.y;
                } else { S[nt][0] = -1e30f; S[nt][1] = -1e30f; }
                if (q1 < NTOK && cok) {
                    float2 bb = __ldg((const float2*)(bmp + q1 * NTOK + c0));
                    S[nt][2] += bb.x; S[nt][3] += bb.y;
                } else { S[nt][2] = -1e30f; S[nt][3] = -1e30f; }
            }

            // ---- softmax (rows r0, q1 spread over lane-quads) ----
            float m0 = -1e30f, m1 = -1e30f;
#pragma unroll
            for (int nt = 0; nt < 14; nt++) {
                m0 = fmaxf(m0, fmaxf(S[nt][0], S[nt][1]));
                m1 = fmaxf(m1, fmaxf(S[nt][2], S[nt][3]));
            }
            m0 = fmaxf(m0, __shfl_xor_sync(0xffffffffu, m0, 1));
            m0 = fmaxf(m0, __shfl_xor_sync(0xffffffffu, m0, 2));
            m1 = fmaxf(m1, __shfl_xor_sync(0xffffffffu, m1, 1));
            m1 = fmaxf(m1, __shfl_xor_sync(0xffffffffu, m1, 2));
            float s0 = 0.0f, s1 = 0.0f;
#pragma unroll
            for (int nt = 0; nt < 14; nt++) {
                S[nt][0] = __expf(S[nt][0] - m0); s0 += S[nt][0];
                S[nt][1] = __expf(S[nt][1] - m0); s0 += S[nt][1];
                S[nt][2] = __expf(S[nt][2] - m1); s1 += S[nt][2];
                S[nt][3] = __expf(S[nt][3] - m1); s1 += S[nt][3];
            }
            s0 += __shfl_xor_sync(0xffffffffu, s0, 1);
            s0 += __shfl_xor_sync(0xffffffffu, s0, 2);
            s1 += __shfl_xor_sync(0xffffffffu, s1, 1);
            s1 += __shfl_xor_sync(0xffffffffu, s1, 2);
            float inv0 = __frcp_rn(s0), inv1 = __frcp_rn(s1);

            // ---- pack P to bf16 hi/lo fragments ----
            uint ph[14][2], pl[14][2];
#pragma unroll
            for (int nt = 0; nt < 14; nt++) {
                float f0 = S[nt][0] * inv0, f1 = S[nt][1] * inv0;
                uint hp = pkbf(f0, f1);
                ph[nt][0] = hp;
                pl[nt][0] = pkbf(f0 - blo(hp), f1 - bhi(hp));
                float f2 = S[nt][2] * inv1, f3 = S[nt][3] * inv1;
                uint hq = pkbf(f2, f3);
                ph[nt][1] = hq;
                pl[nt][1] = pkbf(f2 - blo(hq), f3 - bhi(hq));
            }

            // ---- O[4h..4h+3] += P V  (7 k16 steps, 4 d-tiles) ----
#pragma unroll
            for (int s = 0; s < 7; s++) {
                uint pah[4] = { ph[2 * s][0], ph[2 * s][1], ph[2 * s + 1][0], ph[2 * s + 1][1] };
                uint pal[4] = { pl[2 * s][0], pl[2 * s][1], pl[2 * s + 1][0], pl[2 * s + 1][1] };
#pragma unroll
                for (int nt = 0; nt < 4; nt++) {
                    int vb = (8 * nt + g) * 60 + 8 * s + t;
                    uint bh0 = smw[VTH + vb], bh1 = smw[VTH + vb + 4];
                    uint bl0 = smw[VTL + vb], bl1 = smw[VTL + vb + 4];
                    mma16816(O[4 * h + nt], pah, bh0, bh1);
                    mma16816(O[4 * h + nt], pah, bl0, bl1);
                    mma16816(O[4 * h + nt], pal, bh0, bh1);
                }
            }
        }
    }

    // ================= projection phase =================
    __syncthreads();   // all PV reads of V done before W overwrites smem

    // load + split W: Wh/Wl [128 cols x 68w stride]
    for (int i = tid; i < 8192; i += 256) {
        int c = i >> 6, dp = i & 63;
        float2 w = *(const float2*)(pw + c * DIMM + 2 * dp);
        uint hw_ = pkbf(w.x, w.y);
        smw[WH + c * 68 + dp] = hw_;
        smw[WL + c * 68 + dp] = pkbf(w.x - blo(hw_), w.y - bhi(hw_));
    }
    __syncthreads();

    if (wid >= 7) return;

    // out[r][c] = sum_d O[r][d] * W[c][d] + pb[c]; two nt-halves to cap regs
    float* orow0 = out + ((size_t)b * NTOK + r0) * DIMM;
    float* orow1 = out + ((size_t)b * NTOK + q1) * DIMM;

#pragma unroll
    for (int half = 0; half < 2; half++) {
        float R[8][4];
#pragma unroll
        for (int nt = 0; nt < 8; nt++)
#pragma unroll
            for (int j = 0; j < 4; j++) R[nt][j] = 0.0f;

#pragma unroll
        for (int s = 0; s < 8; s++) {
            int kg0 = 2 * s, kg1 = 2 * s + 1;
            uint ah[4], al[4];
            ah[0] = pkbf(O[kg0][0], O[kg0][1]);
            al[0] = pkbf(O[kg0][0] - blo(ah[0]), O[kg0][1] - bhi(ah[0]));
            ah[1] = pkbf(O[kg0][2], O[kg0][3]);
            al[1] = pkbf(O[kg0][2] - blo(ah[1]), O[kg0][3] - bhi(ah[1]));
            ah[2] = pkbf(O[kg1][0], O[kg1][1]);
            al[2] = pkbf(O[kg1][0] - blo(ah[2]), O[kg1][1] - bhi(ah[2]));
            ah[3] = pkbf(O[kg1][2], O[kg1][3]);
            al[3] = pkbf(O[kg1][2] - blo(ah[3]), O[kg1][3] - bhi(ah[3]));
#pragma unroll
            for (int nt = 0; nt < 8; nt++) {
                int wb = (8 * (half * 8 + nt) + g) * 68 + 8 * s + t;
                uint bh0 = smw[WH + wb], bh1 = smw[WH + wb + 4];
                uint bl0 = smw[WL + wb], bl1 = smw[WL + wb + 4];
                mma16816(R[nt], ah, bh0, bh1);
                mma16816(R[nt], ah, bl0, bl1);
                mma16816(R[nt], al, bh0, bh1);
            }
        }

#pragma unroll
        for (int nt = 0; nt < 8; nt++) {
            int c0 = (half * 8 + nt) * 8 + 2 * t;
            float2 bb = __ldg((const float2*)(pb + c0));
            if (r0 < NTOK) {
                float2 o0 = { R[nt][0] + bb.x, R[nt][1] + bb.y };
                *(float2*)(orow0 + c0) = o0;
            }
            if (q1 < NTOK) {
                float2 o1 = { R[nt][2] + bb.x, R[nt][3] + bb.y };
                *(float2*)(orow1 + c0) = o1;
            }
        }
    }
}

// ---------------------------------------------------------------------------
extern "C" void kernel_launch(void* const* d_in, const int* in_sizes, int n_in,
                              void* d_out, int out_size) {
    const float* x     = (const float*)d_in[0];
    const int*   rpi   = (const int*)d_in[1];      // int32 on the wire
    const float* mask  = (const float*)d_in[2];
    const float* table = (const float*)d_in[3];
    const float* pw    = (const float*)d_in[4];
    const float* pb    = (const float*)d_in[5];
    float*       out   = (float*)d_out;

    const int smem_fused = SMW_TOT * 4;   // 69632 B
    cudaFuncSetAttribute(fused_kernel, cudaFuncAttributeMaxDynamicSharedMemorySize, smem_fused);

    bm_kernel<<<(NWIN * NN + 255) / 256, 256>>>(rpi, table, mask);
    fused_kernel<<<B_WIN, 256, smem_fused>>>(x, pw, pb, out);
}

// round 8
// speedup vs baseline: 4.8325x; 1.0286x over previous
#include <cuda_runtime.h>

#define B_WIN 2048
#define NTOK  98
#define NHEAD 4
#define HD    32
#define C3    384
#define DIMM  128
#define NWIN  64
#define NN    (NTOK * NTOK)   // 9604
#define RPB_ROWS 507

typedef unsigned int uint;

// ---------------- bf16 helpers ----------------
__device__ __forceinline__ uint pkbf(float lo, float hi) {
    uint r; asm("cvt.rn.bf16x2.f32 %0, %1, %2;" : "=r"(r) : "f"(hi), "f"(lo)); return r;
}
__device__ __forceinline__ float blo(uint p) { return __uint_as_float(p << 16); }
__device__ __forceinline__ float bhi(uint p) { return __uint_as_float(p & 0xffff0000u); }

// D += A * B  (m16n8k16, bf16 in, f32 accum)
__device__ __forceinline__ void mma16816(float* d, const uint* a, uint b0, uint b1) {
    asm("mma.sync.aligned.m16n8k16.row.col.f32.bf16.bf16.f32 "
        "{%0,%1,%2,%3}, {%4,%5,%6,%7}, {%8,%9}, {%0,%1,%2,%3};"
        : "+f"(d[0]), "+f"(d[1]), "+f"(d[2]), "+f"(d[3])
        : "r"(a[0]), "r"(a[1]), "r"(a[2]), "r"(a[3]), "r"(b0), "r"(b1));
}

// ---------------- scratch ----------------
__device__ float g_bm[(size_t)NWIN * NHEAD * NN];   // bias + mask (fp32), 9.8 MB

// smem word offsets (attention phase)
#define QH  0
#define QL  2240
#define KH  4480
#define KL  6720
#define VTH 8960
#define VTL 10880
#define QKVW 12800
// smem word offsets (projection phase, overlays QKV)
#define WH  0
#define WL  8704
#define SMW_TOT 17408   // 69632 B

// ---------------------------------------------------------------------------
// Kernel A: g_bm[w][h][q*98+k] = rpb_table[rpi[q,k]][h] + mask[w][q][k]
// ---------------------------------------------------------------------------
__global__ void bm_kernel(const int* __restrict__ rpi,
                          const float* __restrict__ table,
                          const float* __restrict__ mask) {
    int i = blockIdx.x * blockDim.x + threadIdx.x;
    if (i >= NWIN * NN) return;
    int w = i / NN;
    int e = i - w * NN;
    int r = rpi[e];
    r = (r < 0) ? 0 : (r >= RPB_ROWS ? RPB_ROWS - 1 : r);
    float mk = mask[(size_t)w * NN + e];
#pragma unroll
    for (int hh = 0; hh < NHEAD; hh++) {
        g_bm[((size_t)w * NHEAD + hh) * NN + e] = table[r * NHEAD + hh] + mk;
    }
}

// ---------------------------------------------------------------------------
// Fused kernel, streaming softmax-deferred attention + register projection.
// 256 threads, 8 warps (warps 0-6 compute m16 row-blocks; warp 7 load-only).
// ---------------------------------------------------------------------------
__global__ __launch_bounds__(256, 2) void fused_kernel(const float* __restrict__ x,
                                                       const float* __restrict__ pw,
                                                       const float* __restrict__ pb,
                                                       float* __restrict__ out) {
    extern __shared__ uint smw[];

    const int b   = blockIdx.x;
    const int tid = threadIdx.x;
    const int lane = tid & 31;
    const int wid  = tid >> 5;
    const int g = lane >> 2;     // row-in-tile group
    const int t = lane & 3;      // thread in group

    const float scale = 0.17677669529663687f;  // 1/sqrt(32)
    const float* xb = x + (size_t)b * NTOK * C3;
    const int r0 = wid * 16 + g;
    const int q1 = r0 + 8;
    const bool rok0 = (r0 < NTOK), rok1 = (q1 < NTOK);

    // ---- zero QKV region once (covers all row/col pads) ----
    for (int i = tid; i < QKVW; i += 256) smw[i] = 0u;

    // ---- O accumulators: full 128-d for rows r0, q1 ----
    float O[16][4];
#pragma unroll
    for (int nt = 0; nt < 16; nt++)
#pragma unroll
        for (int j = 0; j < 4; j++) O[nt][j] = 0.0f;

#pragma unroll
    for (int h = 0; h < NHEAD; h++) {
        __syncthreads();   // previous head's consumers done (and zero visible)

        // ---- load + split Q(scaled), K, V(transposed) to bf16 hi/lo ----
        for (int i = tid; i < NTOK * 16; i += 256) {
            int q = i >> 4, dp = i & 15;
            const float* base = xb + q * C3 + h * HD + 2 * dp;
            float2 qv = *(const float2*)base;
            qv.x *= scale; qv.y *= scale;
            uint hq = pkbf(qv.x, qv.y);
            smw[QH + q * 20 + dp] = hq;
            smw[QL + q * 20 + dp] = pkbf(qv.x - blo(hq), qv.y - bhi(hq));
            float2 kv = *(const float2*)(base + DIMM);
            uint hk = pkbf(kv.x, kv.y);
            smw[KH + q * 20 + dp] = hk;
            smw[KL + q * 20 + dp] = pkbf(kv.x - blo(hk), kv.y - bhi(hk));
            float2 vv = *(const float2*)(base + 2 * DIMM);
            uint hv = pkbf(vv.x, vv.y);
            uint lv = pkbf(vv.x - blo(hv), vv.y - bhi(hv));
            unsigned short* vth = (unsigned short*)(smw + VTH);
            unsigned short* vtl = (unsigned short*)(smw + VTL);
            int d0 = 2 * dp;
            vth[d0 * 120 + q]       = (unsigned short)(hv & 0xffffu);
            vth[(d0 + 1) * 120 + q] = (unsigned short)(hv >> 16);
            vtl[d0 * 120 + q]       = (unsigned short)(lv & 0xffffu);
            vtl[(d0 + 1) * 120 + q] = (unsigned short)(lv >> 16);
        }
        __syncthreads();

        if (wid < 7) {
            // ---- Q A-fragments (hoisted: both k-steps, hi+lo) ----
            uint qah[2][4], qal[2][4];
#pragma unroll
            for (int s = 0; s < 2; s++) {
                int ab = r0 * 20 + 8 * s + t;
                qah[s][0] = smw[QH + ab];       qah[s][1] = smw[QH + ab + 160];
                qah[s][2] = smw[QH + ab + 4];   qah[s][3] = smw[QH + ab + 164];
                qal[s][0] = smw[QL + ab];       qal[s][1] = smw[QL + ab + 160];
                qal[s][2] = smw[QL + ab + 4];   qal[s][3] = smw[QL + ab + 164];
            }

            const float* bmp = g_bm + ((size_t)(b & (NWIN - 1)) * NHEAD + h) * NN;
            float s0 = 0.0f, s1 = 0.0f;
            float* Oh = &O[4 * h][0];   // 4 contiguous tiles for this head

            // ---- stream over k16 chunks: S pair -> exp -> pack -> PV ----
#pragma unroll
            for (int c = 0; c < 7; c++) {
                float Sp[2][4];
#pragma unroll
                for (int u = 0; u < 2; u++)
#pragma unroll
                    for (int j = 0; j < 4; j++) Sp[u][j] = 0.0f;

#pragma unroll
                for (int u = 0; u < 2; u++) {
                    int nt = 2 * c + u;
#pragma unroll
                    for (int s = 0; s < 2; s++) {
                        int kb = (8 * nt + g) * 20 + 8 * s + t;
                        uint bh0 = smw[KH + kb], bh1 = smw[KH + kb + 4];
                        uint bl0 = smw[KL + kb], bl1 = smw[KL + kb + 4];
                        mma16816(Sp[u], qah[s], bh0, bh1);
                        mma16816(Sp[u], qah[s], bl0, bl1);
                        mma16816(Sp[u], qal[s], bh0, bh1);
                    }
                    // bias + mask + padding, then exp (no max subtract: logits small)
                    int c0 = nt * 8 + 2 * t;
                    bool cok = (c0 < NTOK);
                    if (rok0 && cok) {
                        float2 bb = __ldg((const float2*)(bmp + r0 * NTOK + c0));
                        Sp[u][0] += bb.x; Sp[u][1] += bb.y;
                    } else { Sp[u][0] = -1e30f; Sp[u][1] = -1e30f; }
                    if (rok1 && cok) {
                        float2 bb = __ldg((const float2*)(bmp + q1 * NTOK + c0));
                        Sp[u][2] += bb.x; Sp[u][3] += bb.y;
                    } else { Sp[u][2] = -1e30f; Sp[u][3] = -1e30f; }
                    Sp[u][0] = __expf(Sp[u][0]); s0 += Sp[u][0];
                    Sp[u][1] = __expf(Sp[u][1]); s0 += Sp[u][1];
                    Sp[u][2] = __expf(Sp[u][2]); s1 += Sp[u][2];
                    Sp[u][3] = __expf(Sp[u][3]); s1 += Sp[u][3];
                }

                // pack unnormalized P to bf16 hi/lo A-fragment for this k16 chunk
                uint pah[4], pal[4];
                pah[0] = pkbf(Sp[0][0], Sp[0][1]);
                pal[0] = pkbf(Sp[0][0] - blo(pah[0]), Sp[0][1] - bhi(pah[0]));
                pah[1] = pkbf(Sp[0][2], Sp[0][3]);
                pal[1] = pkbf(Sp[0][2] - blo(pah[1]), Sp[0][3] - bhi(pah[1]));
                pah[2] = pkbf(Sp[1][0], Sp[1][1]);
                pal[2] = pkbf(Sp[1][0] - blo(pah[2]), Sp[1][1] - bhi(pah[2]));
                pah[3] = pkbf(Sp[1][2], Sp[1][3]);
                pal[3] = pkbf(Sp[1][2] - blo(pah[3]), Sp[1][3] - bhi(pah[3]));

                // PV accumulate: 4 d-tiles
#pragma unroll
                for (int nt = 0; nt < 4; nt++) {
                    int vb = (8 * nt + g) * 60 + 8 * c + t;
                    uint bh0 = smw[VTH + vb], bh1 = smw[VTH + vb + 4];
                    uint bl0 = smw[VTL + vb], bl1 = smw[VTL + vb + 4];
                    mma16816(&Oh[4 * nt], pah, bh0, bh1);
                    mma16816(&Oh[4 * nt], pah, bl0, bl1);
                    mma16816(&Oh[4 * nt], pal, bh0, bh1);
                }
            }

            // ---- deferred normalization: O *= 1/rowsum ----
            s0 += __shfl_xor_sync(0xffffffffu, s0, 1);
            s0 += __shfl_xor_sync(0xffffffffu, s0, 2);
            s1 += __shfl_xor_sync(0xffffffffu, s1, 1);
            s1 += __shfl_xor_sync(0xffffffffu, s1, 2);
            float inv0 = __frcp_rn(s0), inv1 = __frcp_rn(s1);
#pragma unroll
            for (int nt = 0; nt < 4; nt++) {
                Oh[4 * nt + 0] *= inv0;
                Oh[4 * nt + 1] *= inv0;
                Oh[4 * nt + 2] *= inv1;
                Oh[4 * nt + 3] *= inv1;
            }
        }
    }

    // ================= projection phase =================
    __syncthreads();   // all PV reads of V done before W overwrites smem

    // load + split W: Wh/Wl [128 cols x 68w stride]
    for (int i = tid; i < 8192; i += 256) {
        int c = i >> 6, dp = i & 63;
        float2 w = *(const float2*)(pw + c * DIMM + 2 * dp);
        uint hw_ = pkbf(w.x, w.y);
        smw[WH + c * 68 + dp] = hw_;
        smw[WL + c * 68 + dp] = pkbf(w.x - blo(hw_), w.y - bhi(hw_));
    }
    __syncthreads();

    if (wid >= 7) return;

    float* orow0 = out + ((size_t)b * NTOK + r0) * DIMM;
    float* orow1 = out + ((size_t)b * NTOK + q1) * DIMM;

#pragma unroll
    for (int half = 0; half < 2; half++) {
        float R[8][4];
#pragma unroll
        for (int nt = 0; nt < 8; nt++)
#pragma unroll
            for (int j = 0; j < 4; j++) R[nt][j] = 0.0f;

#pragma unroll
        for (int s = 0; s < 8; s++) {
            int kg0 = 2 * s, kg1 = 2 * s + 1;
            uint ah[4], al[4];
            ah[0] = pkbf(O[kg0][0], O[kg0][1]);
            al[0] = pkbf(O[kg0][0] - blo(ah[0]), O[kg0][1] - bhi(ah[0]));
            ah[1] = pkbf(O[kg0][2], O[kg0][3]);
            al[1] = pkbf(O[kg0][2] - blo(ah[1]), O[kg0][3] - bhi(ah[1]));
            ah[2] = pkbf(O[kg1][0], O[kg1][1]);
            al[2] = pkbf(O[kg1][0] - blo(ah[2]), O[kg1][1] - bhi(ah[2]));
            ah[3] = pkbf(O[kg1][2], O[kg1][3]);
            al[3] = pkbf(O[kg1][2] - blo(ah[3]), O[kg1][3] - bhi(ah[3]));
#pragma unroll
            for (int nt = 0; nt < 8; nt++) {
                int wb = (8 * (half * 8 + nt) + g) * 68 + 8 * s + t;
                uint bh0 = smw[WH + wb], bh1 = smw[WH + wb + 4];
                uint bl0 = smw[WL + wb], bl1 = smw[WL + wb + 4];
                mma16816(R[nt], ah, bh0, bh1);
                mma16816(R[nt], ah, bl0, bl1);
                mma16816(R[nt], al, bh0, bh1);
            }
        }

#pragma unroll
        for (int nt = 0; nt < 8; nt++) {
            int c0 = (half * 8 + nt) * 8 + 2 * t;
            float2 bb = __ldg((const float2*)(pb + c0));
            if (rok0) {
                float2 o0 = { R[nt][0] + bb.x, R[nt][1] + bb.y };
                *(float2*)(orow0 + c0) = o0;
            }
            if (rok1) {
                float2 o1 = { R[nt][2] + bb.x, R[nt][3] + bb.y };
                *(float2*)(orow1 + c0) = o1;
            }
        }
    }
}

// ---------------------------------------------------------------------------
extern "C" void kernel_launch(void* const* d_in, const int* in_sizes, int n_in,
                              void* d_out, int out_size) {
    const float* x     = (const float*)d_in[0];
    const int*   rpi   = (const int*)d_in[1];      // int32 on the wire
    const float* mask  = (const float*)d_in[2];
    const float* table = (const float*)d_in[3];
    const float* pw    = (const float*)d_in[4];
    const float* pb    = (const float*)d_in[5];
    float*       out   = (float*)d_out;

    const int smem_fused = SMW_TOT * 4;   // 69632 B
    cudaFuncSetAttribute(fused_kernel, cudaFuncAttributeMaxDynamicSharedMemorySize, smem_fused);

    bm_kernel<<<(NWIN * NN + 255) / 256, 256>>>(rpi, table, mask);
    fused_kernel<<<B_WIN, 256, smem_fused>>>(x, pw, pb, out);
}